// round 15
// baseline (speedup 1.0000x reference)
#include <cuda_runtime.h>
#include <cuda_bf16.h>
#include <cuda_fp16.h>
#include <math.h>

// Problem constants
#define NN     8192
#define F_IN   512
#define F_OUT  256
#define MM     4096
#define NEG_SLOPE 0.01f
#define MAXNBR 512

// ---------------------------------------------------------------------------
// Scratch
// ---------------------------------------------------------------------------
__device__ float  g_z [NN * F_OUT];     // 8 MB fp32 z (exact residual term)
__device__ __half g_zh[NN * F_OUT];     // 4 MB fp16 z (for the gather)
__device__ float  g_zi[NN];
__device__ float  g_zj[NN];
__device__ int    g_flag[NN];           // 1 if node appears in node_mask
__device__ int    g_nbr[NN * MAXNBR];   // per-unique-node neighbor lists
__device__ int    g_cnt[NN];
__device__ float  g_h[NN * F_OUT];      // per-unique-node final rows (post-relu)
__device__ __nv_bfloat16 g_Wh[F_OUT * F_IN];  // pre-split W (hi bf16)
__device__ __nv_bfloat16 g_Wl[F_OUT * F_IN];  // pre-split W (lo bf16 residual)

// ---------------------------------------------------------------------------
// split helper (also used by the W pre-split kernel)
// ---------------------------------------------------------------------------
__device__ __forceinline__ void split2(float x, float y, unsigned& hi, unsigned& lo) {
    __nv_bfloat16 hx = __float2bfloat16(x);
    __nv_bfloat16 hy = __float2bfloat16(y);
    float rx = x - __bfloat162float(hx);
    float ry = y - __bfloat162float(hy);
    __nv_bfloat162 h = __halves2bfloat162(hx, hy);
    __nv_bfloat162 l = __halves2bfloat162(__float2bfloat16(rx), __float2bfloat16(ry));
    hi = *reinterpret_cast<unsigned*>(&h);
    lo = *reinterpret_cast<unsigned*>(&l);
}

// ---------------------------------------------------------------------------
// W pre-split: one pass, 0.5 MB -> 2x 0.25 MB bf16. Removes 80% of the
// in-GEMM conversion ALU and halves the GEMM's B-side load bytes.
// ---------------------------------------------------------------------------
__global__ __launch_bounds__(256) void presplit_w_kernel(const float* __restrict__ Wm)
{
    int i = (blockIdx.x * 256 + threadIdx.x) * 2;   // over 256*512 elems
    float2 v = *(const float2*)&Wm[i];
    unsigned h, l;
    split2(v.x, v.y, h, l);
    *(unsigned*)&g_Wh[i] = h;
    *(unsigned*)&g_Wl[i] = l;
}

// ---------------------------------------------------------------------------
// Kernel A: z = feats @ W^T + b via 3x bf16 m16n8k16 (hi/lo split),
// CTA 64x256, 256 threads = 8 warps (2x4), warp tile 32x64,
// register-prefetch double buffering. B side now loads PRE-SPLIT bf16
// (uint4 LDG -> STS.128, no conversion). smem layout identical to R14,
// so all MMA fragment indexing is unchanged.
// ---------------------------------------------------------------------------
#define BM 64
#define BN 256
#define BK 32
#define SAW 20   // 32-bit words per smem row (= 40 bf16)

#define AW  (64 * SAW)
#define BW  (256 * SAW)
#define GEMM_SMEM ((AW + AW + BW + BW) * 4 + 64 * 4 * 4 * 2)

__device__ __forceinline__ void mma_bf16(float* d, const unsigned* a, const unsigned* b) {
    asm volatile(
        "mma.sync.aligned.m16n8k16.row.col.f32.bf16.bf16.f32 "
        "{%0,%1,%2,%3}, {%4,%5,%6,%7}, {%8,%9}, {%0,%1,%2,%3};\n"
        : "+f"(d[0]), "+f"(d[1]), "+f"(d[2]), "+f"(d[3])
        : "r"(a[0]), "r"(a[1]), "r"(a[2]), "r"(a[3]), "r"(b[0]), "r"(b[1]));
}

__global__ __launch_bounds__(256) void gemm_z_tc(
    const float* __restrict__ A,     // feats [8192,512]
    const float* __restrict__ bias,
    const float* __restrict__ a1v,
    const float* __restrict__ a2v)
{
    extern __shared__ char smem_raw[];
    unsigned* Ah = (unsigned*)smem_raw;          // 64*20 words
    unsigned* Al = Ah + AW;
    unsigned* Bh = Al + AW;                      // 256*20 words
    unsigned* Bl = Bh + BW;
    float* redbase = (float*)(Bl + BW);
    float (*s_red1)[4] = (float(*)[4])redbase;
    float (*s_red2)[4] = (float(*)[4])(redbase + 64 * 4);

    const int tid  = threadIdx.x;
    const int lane = tid & 31;
    const int warp = tid >> 5;
    const int wm   = warp >> 2;      // 0..1
    const int wn   = warp & 3;       // 0..3
    const int rowBase = blockIdx.x * BM;

    float acc[2][8][4];
#pragma unroll
    for (int mt = 0; mt < 2; mt++)
#pragma unroll
        for (int nt = 0; nt < 8; nt++)
#pragma unroll
            for (int r = 0; r < 4; r++) acc[mt][nt][r] = 0.f;

    // Register prefetch buffers.
    // A: 2 float4/thread (fp32, split in-kernel).
    // B: 4+4 uint4/thread of pre-split bf16 (straight to smem).
    float4 pa[2];
    uint4  pbh[4], pbl[4];

    const int bn = tid >> 2, bq = tid & 3;     // B: row 0..255 (per p stride 64), quad
#pragma unroll
    for (int p = 0; p < 2; p++) {
        int lin = tid + p * 256;
        int r = lin >> 3, kq = lin & 7;
        pa[p] = *(const float4*)&A[(size_t)(rowBase + r) * F_IN + kq * 4];
    }
#pragma unroll
    for (int p = 0; p < 4; p++) {
        int n = bn + p * 64;
        pbh[p] = *(const uint4*)&g_Wh[n * F_IN + bq * 8];
        pbl[p] = *(const uint4*)&g_Wl[n * F_IN + bq * 8];
    }

    for (int k0 = 0; k0 < F_IN; k0 += BK) {
        // Commit prefetched tile to smem
#pragma unroll
        for (int p = 0; p < 2; p++) {
            int lin = tid + p * 256;
            int r = lin >> 3, kq = lin & 7;
            unsigned h01, l01, h23, l23;
            split2(pa[p].x, pa[p].y, h01, l01);
            split2(pa[p].z, pa[p].w, h23, l23);
            int w = r * SAW + kq * 2;
            Ah[w] = h01; Ah[w + 1] = h23;
            Al[w] = l01; Al[w + 1] = l23;
        }
#pragma unroll
        for (int p = 0; p < 4; p++) {
            int n = bn + p * 64;
            int w = n * SAW + bq * 4;          // byte addr = n*80 + bq*16: 16B aligned
            *(uint4*)&Bh[w] = pbh[p];
            *(uint4*)&Bl[w] = pbl[p];
        }
        __syncthreads();

        // Early LDG of next tile (overlaps MMA below)
        if (k0 + BK < F_IN) {
            int kn = k0 + BK;
#pragma unroll
            for (int p = 0; p < 2; p++) {
                int lin = tid + p * 256;
                int r = lin >> 3, kq = lin & 7;
                pa[p] = *(const float4*)&A[(size_t)(rowBase + r) * F_IN + kn + kq * 4];
            }
#pragma unroll
            for (int p = 0; p < 4; p++) {
                int n = bn + p * 64;
                pbh[p] = *(const uint4*)&g_Wh[n * F_IN + kn + bq * 8];
                pbl[p] = *(const uint4*)&g_Wl[n * F_IN + kn + bq * 8];
            }
        }

        // Two k16 steps per BK=32 tile
#pragma unroll
        for (int kk = 0; kk < 2; kk++) {
            const int kb = kk * 8 + (lane & 3);
            unsigned ah[2][4], al[2][4];
#pragma unroll
            for (int mt = 0; mt < 2; mt++) {
                int r0 = (wm * 32 + mt * 16 + (lane >> 2)) * SAW;
                int r8 = r0 + 8 * SAW;
                ah[mt][0] = Ah[r0 + kb];     ah[mt][1] = Ah[r8 + kb];
                ah[mt][2] = Ah[r0 + kb + 4]; ah[mt][3] = Ah[r8 + kb + 4];
                al[mt][0] = Al[r0 + kb];     al[mt][1] = Al[r8 + kb];
                al[mt][2] = Al[r0 + kb + 4]; al[mt][3] = Al[r8 + kb + 4];
            }
#pragma unroll
            for (int nt = 0; nt < 8; nt++) {
                int nb = (wn * 64 + nt * 8 + (lane >> 2)) * SAW;
                unsigned bh[2] = { Bh[nb + kb], Bh[nb + kb + 4] };
                unsigned bl[2] = { Bl[nb + kb], Bl[nb + kb + 4] };
#pragma unroll
                for (int mt = 0; mt < 2; mt++) {
                    mma_bf16(acc[mt][nt], ah[mt], bh);   // hi*hi
                    mma_bf16(acc[mt][nt], ah[mt], bl);   // hi*lo
                    mma_bf16(acc[mt][nt], al[mt], bh);   // lo*hi
                }
            }
        }
        __syncthreads();
    }

    // Epilogue: +bias, store z (fp32 + fp16), fused zi/zj
    float s1[4] = {0.f, 0.f, 0.f, 0.f};
    float s2[4] = {0.f, 0.f, 0.f, 0.f};
#pragma unroll
    for (int mt = 0; mt < 2; mt++) {
#pragma unroll
        for (int nt = 0; nt < 8; nt++) {
            int c = wn * 64 + nt * 8 + 2 * (lane & 3);
            float b0 = bias[c], b1 = bias[c + 1];
            float v00 = acc[mt][nt][0] + b0;
            float v01 = acc[mt][nt][1] + b1;
            float v10 = acc[mt][nt][2] + b0;
            float v11 = acc[mt][nt][3] + b1;
            int r0 = rowBase + wm * 32 + mt * 16 + (lane >> 2);
            *(float2*)&g_z[(size_t)r0 * F_OUT + c]       = make_float2(v00, v01);
            *(float2*)&g_z[(size_t)(r0 + 8) * F_OUT + c] = make_float2(v10, v11);
            *(__half2*)&g_zh[(size_t)r0 * F_OUT + c]       = __floats2half2_rn(v00, v01);
            *(__half2*)&g_zh[(size_t)(r0 + 8) * F_OUT + c] = __floats2half2_rn(v10, v11);
            float a1c = a1v[c], a1c1 = a1v[c + 1];
            float a2c = a2v[c], a2c1 = a2v[c + 1];
            s1[mt * 2 + 0] += a1c * v00 + a1c1 * v01;
            s1[mt * 2 + 1] += a1c * v10 + a1c1 * v11;
            s2[mt * 2 + 0] += a2c * v00 + a2c1 * v01;
            s2[mt * 2 + 1] += a2c * v10 + a2c1 * v11;
        }
    }
#pragma unroll
    for (int i = 0; i < 4; i++) {
        s1[i] += __shfl_xor_sync(0xffffffffu, s1[i], 1);
        s1[i] += __shfl_xor_sync(0xffffffffu, s1[i], 2);
        s2[i] += __shfl_xor_sync(0xffffffffu, s2[i], 1);
        s2[i] += __shfl_xor_sync(0xffffffffu, s2[i], 2);
    }
    if ((lane & 3) == 0) {
#pragma unroll
        for (int i = 0; i < 4; i++) {
            int mt = i >> 1, h = i & 1;
            int rl = wm * 32 + mt * 16 + (lane >> 2) + h * 8;
            s_red1[rl][wn] = s1[i];
            s_red2[rl][wn] = s2[i];
        }
    }
    __syncthreads();
    if (tid < BM) {
        g_zi[rowBase + tid] = s_red1[tid][0] + s_red1[tid][1] + s_red1[tid][2] + s_red1[tid][3];
    } else if (tid < 2 * BM) {
        int r = tid - BM;
        g_zj[rowBase + r] = s_red2[r][0] + s_red2[r][1] + s_red2[r][2] + s_red2[r][3];
    }
}

// ---------------------------------------------------------------------------
// Flag kernels: mark unique masked nodes (dedup: ~3224 of 8192).
// ---------------------------------------------------------------------------
__global__ __launch_bounds__(1024) void zero_flags_kernel() {
    int i = blockIdx.x * 1024 + threadIdx.x;
    if (i < NN) g_flag[i] = 0;
}
__global__ __launch_bounds__(256) void set_flags_kernel(const int* __restrict__ mask) {
    int m = blockIdx.x * 256 + threadIdx.x;
    if (m < MM) g_flag[mask[m]] = 1;
}

// ---------------------------------------------------------------------------
// Kernel B [R11/R14, measured 21.9-22.4us, 40 regs]: bitmask scan of adj rows
// of unique masked nodes -> neighbor lists. Co-resides with GEMM CTAs.
// ---------------------------------------------------------------------------
__global__ __launch_bounds__(256, 6) void scan_kernel(const float* __restrict__ adj)
{
    __shared__ int s_idx[MAXNBR];
    __shared__ int s_cnt;

    const int i = blockIdx.x;
    if (!g_flag[i]) return;
    const int tid = threadIdx.x;
    const int lane = tid & 31;

    if (tid == 0) s_cnt = 0;
    __syncthreads();

    const float4* arow = (const float4*)(adj + (size_t)i * NN);

    unsigned msk = 0;
#pragma unroll
    for (int q = 0; q < 8; q++) {
        float4 v = arow[q * 256 + tid];
        msk |= (unsigned)(v.x != 0.f) << (q * 4 + 0);
        msk |= (unsigned)(v.y != 0.f) << (q * 4 + 1);
        msk |= (unsigned)(v.z != 0.f) << (q * 4 + 2);
        msk |= (unsigned)(v.w != 0.f) << (q * 4 + 3);
    }

    int c = __popc(msk);
    int pref = c;
#pragma unroll
    for (int d = 1; d < 32; d <<= 1) {
        int n = __shfl_up_sync(0xffffffffu, pref, d);
        if (lane >= d) pref += n;
    }
    int total = __shfl_sync(0xffffffffu, pref, 31);
    int base = 0;
    if (lane == 31) base = atomicAdd(&s_cnt, total);
    base = __shfl_sync(0xffffffffu, base, 31);
    int pos = base + pref - c;

    while (msk) {
        int b = __ffs(msk) - 1;
        msk &= msk - 1;
        int j = ((b >> 2) << 10) + tid * 4 + (b & 3);
        if (pos < MAXNBR) s_idx[pos++] = j;
    }
    __syncthreads();

    int cnt = s_cnt;
    if (cnt > MAXNBR) cnt = MAXNBR;
    for (int k = tid; k < cnt; k += 256)
        g_nbr[i * MAXNBR + k] = s_idx[k];
    if (tid == 0) g_cnt[i] = cnt;
}

// ---------------------------------------------------------------------------
// Kernel C [R9/R14]: per unique node, gather fp16 z over neighbors,
// closed-form attention combine vs fp32 z/zi/zj, relu, store g_h[node].
// ---------------------------------------------------------------------------
__global__ __launch_bounds__(128) void combine_kernel()
{
    __shared__ int s_idx[MAXNBR];

    const int i = blockIdx.x;
    if (!g_flag[i]) return;
    const int tid = threadIdx.x;
    const int cnt = g_cnt[i];

    for (int k = tid; k < cnt; k += 128) s_idx[k] = g_nbr[i * MAXNBR + k];
    __syncthreads();

    const __half2* zh2 = (const __half2*)g_zh;
    float ax = 0.f, ay = 0.f;
    int k = 0;
    for (; k + 8 <= cnt; k += 8) {
        float2 t[8];
#pragma unroll
        for (int u = 0; u < 8; u++) {
            __half2 h = zh2[(size_t)s_idx[k + u] * (F_OUT / 2) + tid];
            t[u] = __half22float2(h);
        }
#pragma unroll
        for (int u = 0; u < 8; u++) { ax += t[u].x; ay += t[u].y; }
    }
    for (; k < cnt; k++) {
        float2 t = __half22float2(zh2[(size_t)s_idx[k] * (F_OUT / 2) + tid]);
        ax += t.x; ay += t.y;
    }

    float2 zv = *(const float2*)&g_z[(size_t)i * F_OUT + 2 * tid];
    float vi = g_zi[i];
    float vj = g_zj[i];

    float x_off  = vi;
    float x_diag = vi + vj;
    float l_off  = x_off  > 0.f ? x_off  : NEG_SLOPE * x_off;
    float l_diag = x_diag > 0.f ? x_diag : NEG_SLOPE * x_diag;
    float e_off  = expf(l_off);
    float e_diag = expf(l_diag);
    float S = (float)(cnt - 1) * e_off + e_diag;
    float invS = 1.0f / S;
    float eS = e_off * invS, dS = e_diag * invS;

    float hx = zv.x - (eS * (ax - zv.x) + dS * zv.x);
    float hy = zv.y - (eS * (ay - zv.y) + dS * zv.y);
    *(float2*)&g_h[(size_t)i * F_OUT + 2 * tid] =
        make_float2(fmaxf(hx, 0.f), fmaxf(hy, 0.f));
}

// ---------------------------------------------------------------------------
// Kernel D: out[m] = g_h[mask[m]]   (flat float4 copy)
// ---------------------------------------------------------------------------
__global__ __launch_bounds__(256) void out_copy_kernel(
    const int* __restrict__ mask, float* __restrict__ out)
{
    int idx = blockIdx.x * 256 + threadIdx.x;    // over MM*64 float4 slots
    int m = idx >> 6;
    int t = idx & 63;
    if (m >= MM) return;
    int node = mask[m];
    const float4* src = (const float4*)(g_h + (size_t)node * F_OUT);
    ((float4*)(out + (size_t)m * F_OUT))[t] = src[t];
}

// ---------------------------------------------------------------------------
// Side stream + events (static init; serial fallback if creation fails)
// ---------------------------------------------------------------------------
namespace {
struct StreamRes {
    cudaStream_t s1 = nullptr;
    cudaEvent_t fork = nullptr, scan_done = nullptr;
    bool ok = false;
    StreamRes() {
        if (cudaStreamCreateWithFlags(&s1, cudaStreamNonBlocking) != cudaSuccess) return;
        if (cudaEventCreateWithFlags(&fork, cudaEventDisableTiming) != cudaSuccess) return;
        if (cudaEventCreateWithFlags(&scan_done, cudaEventDisableTiming) != cudaSuccess) return;
        ok = true;
    }
};
StreamRes g_sr;
}

// ---------------------------------------------------------------------------
// Launch.  Inputs: 0 adj, 1 eye (UNUSED), 2 feats, 3 node_mask, 4 W, 5 b,
//                  6 a_1, 7 a_2.   Output [M,256] f32.
// ---------------------------------------------------------------------------
extern "C" void kernel_launch(void* const* d_in, const int* in_sizes, int n_in,
                              void* d_out, int out_size)
{
    const float* adj   = (const float*)d_in[0];
    const float* feats = (const float*)d_in[2];
    const int*   maskp = (const int*)  d_in[3];
    const float* Wm    = (const float*)d_in[4];
    const float* bias  = (const float*)d_in[5];
    const float* a1    = (const float*)d_in[6];
    const float* a2    = (const float*)d_in[7];
    float* out = (float*)d_out;

    cudaFuncSetAttribute(gemm_z_tc, cudaFuncAttributeMaxDynamicSharedMemorySize, GEMM_SMEM);

    if (g_sr.ok) {
        // Fork: W-presplit + GEMM on main; flags + scan chain on side stream.
        cudaEventRecord(g_sr.fork, 0);
        cudaStreamWaitEvent(g_sr.s1, g_sr.fork, 0);
        presplit_w_kernel<<<(F_OUT * F_IN / 2) / 256, 256>>>(Wm);
        gemm_z_tc<<<NN / BM, 256, GEMM_SMEM>>>(feats, bias, a1, a2);
        zero_flags_kernel<<<(NN + 1023) / 1024, 1024, 0, g_sr.s1>>>();
        set_flags_kernel<<<(MM + 255) / 256, 256, 0, g_sr.s1>>>(maskp);
        scan_kernel<<<NN, 256, 0, g_sr.s1>>>(adj);
        cudaEventRecord(g_sr.scan_done, g_sr.s1);
        cudaStreamWaitEvent(0, g_sr.scan_done, 0);
    } else {
        zero_flags_kernel<<<(NN + 1023) / 1024, 1024>>>();
        set_flags_kernel<<<(MM + 255) / 256, 256>>>(maskp);
        scan_kernel<<<NN, 256>>>(adj);
        presplit_w_kernel<<<(F_OUT * F_IN / 2) / 256, 256>>>(Wm);
        gemm_z_tc<<<NN / BM, 256, GEMM_SMEM>>>(feats, bias, a1, a2);
    }

    combine_kernel<<<NN, 128>>>();
    out_copy_kernel<<<(MM * 64 + 255) / 256, 256>>>(maskp, out);
}

// round 16
// speedup vs baseline: 1.0800x; 1.0800x over previous
#include <cuda_runtime.h>
#include <cuda_bf16.h>
#include <cuda_fp16.h>
#include <math.h>

// Problem constants
#define NN     8192
#define F_IN   512
#define F_OUT  256
#define MM     4096
#define NEG_SLOPE 0.01f
#define MAXNBR 512

// ---------------------------------------------------------------------------
// Scratch
// ---------------------------------------------------------------------------
__device__ float  g_z [NN * F_OUT];     // 8 MB fp32 z (exact residual term)
__device__ __half g_zh[NN * F_OUT];     // 4 MB fp16 z (for the gather)
__device__ float  g_zi[NN];
__device__ float  g_zj[NN];
__device__ int    g_flag[NN];           // 1 if node appears in node_mask
__device__ int    g_nbr[NN * MAXNBR];   // per-unique-node neighbor lists
__device__ int    g_cnt[NN];
__device__ float  g_h[NN * F_OUT];      // per-unique-node final rows (post-relu)

// ---------------------------------------------------------------------------
// Kernel A [R7/R14 version, measured 31.8us, 184 regs -> 18432 regs/SM free]:
// z = feats @ W^T + b via 3x bf16 m16n8k16 (hi/lo split), CTA 64x256,
// 256 threads = 8 warps (2x4), warp tile 32x64, register-prefetch DB.
// Full N per CTA -> zi/zj fused in epilogue.
// ---------------------------------------------------------------------------
#define BM 64
#define BN 256
#define BK 32
#define SAW 20   // 32-bit words per smem row (= 40 bf16)

#define AW  (64 * SAW)
#define BW  (256 * SAW)
#define GEMM_SMEM ((AW + AW + BW + BW) * 4 + 64 * 4 * 4 * 2)

__device__ __forceinline__ void mma_bf16(float* d, const unsigned* a, const unsigned* b) {
    asm volatile(
        "mma.sync.aligned.m16n8k16.row.col.f32.bf16.bf16.f32 "
        "{%0,%1,%2,%3}, {%4,%5,%6,%7}, {%8,%9}, {%0,%1,%2,%3};\n"
        : "+f"(d[0]), "+f"(d[1]), "+f"(d[2]), "+f"(d[3])
        : "r"(a[0]), "r"(a[1]), "r"(a[2]), "r"(a[3]), "r"(b[0]), "r"(b[1]));
}

__device__ __forceinline__ void split2(float x, float y, unsigned& hi, unsigned& lo) {
    __nv_bfloat16 hx = __float2bfloat16(x);
    __nv_bfloat16 hy = __float2bfloat16(y);
    float rx = x - __bfloat162float(hx);
    float ry = y - __bfloat162float(hy);
    __nv_bfloat162 h = __halves2bfloat162(hx, hy);
    __nv_bfloat162 l = __halves2bfloat162(__float2bfloat16(rx), __float2bfloat16(ry));
    hi = *reinterpret_cast<unsigned*>(&h);
    lo = *reinterpret_cast<unsigned*>(&l);
}

__global__ __launch_bounds__(256) void gemm_z_tc(
    const float* __restrict__ A,     // feats [8192,512]
    const float* __restrict__ Wm,    // W [256,512]
    const float* __restrict__ bias,
    const float* __restrict__ a1v,
    const float* __restrict__ a2v)
{
    extern __shared__ char smem_raw[];
    unsigned* Ah = (unsigned*)smem_raw;          // 64*20 words
    unsigned* Al = Ah + AW;
    unsigned* Bh = Al + AW;                      // 256*20 words
    unsigned* Bl = Bh + BW;
    float* redbase = (float*)(Bl + BW);
    float (*s_red1)[4] = (float(*)[4])redbase;
    float (*s_red2)[4] = (float(*)[4])(redbase + 64 * 4);

    const int tid  = threadIdx.x;
    const int lane = tid & 31;
    const int warp = tid >> 5;
    const int wm   = warp >> 2;      // 0..1
    const int wn   = warp & 3;       // 0..3
    const int rowBase = blockIdx.x * BM;

    float acc[2][8][4];
#pragma unroll
    for (int mt = 0; mt < 2; mt++)
#pragma unroll
        for (int nt = 0; nt < 8; nt++)
#pragma unroll
            for (int r = 0; r < 4; r++) acc[mt][nt][r] = 0.f;

    // Register prefetch buffers (next tile)
    float4 pa[2], pb[8];
#pragma unroll
    for (int p = 0; p < 2; p++) {
        int lin = tid + p * 256;
        int r = lin >> 3, kq = lin & 7;
        pa[p] = *(const float4*)&A[(size_t)(rowBase + r) * F_IN + kq * 4];
    }
#pragma unroll
    for (int p = 0; p < 8; p++) {
        int lin = tid + p * 256;
        int n = lin >> 3, kq = lin & 7;
        pb[p] = *(const float4*)&Wm[(size_t)n * F_IN + kq * 4];
    }

    for (int k0 = 0; k0 < F_IN; k0 += BK) {
        // Commit prefetched tile: split hi/lo once, store bf16
#pragma unroll
        for (int p = 0; p < 2; p++) {
            int lin = tid + p * 256;
            int r = lin >> 3, kq = lin & 7;
            unsigned h01, l01, h23, l23;
            split2(pa[p].x, pa[p].y, h01, l01);
            split2(pa[p].z, pa[p].w, h23, l23);
            int w = r * SAW + kq * 2;
            Ah[w] = h01; Ah[w + 1] = h23;
            Al[w] = l01; Al[w + 1] = l23;
        }
#pragma unroll
        for (int p = 0; p < 8; p++) {
            int lin = tid + p * 256;
            int n = lin >> 3, kq = lin & 7;
            unsigned h01, l01, h23, l23;
            split2(pb[p].x, pb[p].y, h01, l01);
            split2(pb[p].z, pb[p].w, h23, l23);
            int w = n * SAW + kq * 2;
            Bh[w] = h01; Bh[w + 1] = h23;
            Bl[w] = l01; Bl[w + 1] = l23;
        }
        __syncthreads();

        // Early LDG of next tile (overlaps MMA below)
        if (k0 + BK < F_IN) {
            int kn = k0 + BK;
#pragma unroll
            for (int p = 0; p < 2; p++) {
                int lin = tid + p * 256;
                int r = lin >> 3, kq = lin & 7;
                pa[p] = *(const float4*)&A[(size_t)(rowBase + r) * F_IN + kn + kq * 4];
            }
#pragma unroll
            for (int p = 0; p < 8; p++) {
                int lin = tid + p * 256;
                int n = lin >> 3, kq = lin & 7;
                pb[p] = *(const float4*)&Wm[(size_t)n * F_IN + kn + kq * 4];
            }
        }

        // Two k16 steps per BK=32 tile
#pragma unroll
        for (int kk = 0; kk < 2; kk++) {
            const int kb = kk * 8 + (lane & 3);
            unsigned ah[2][4], al[2][4];
#pragma unroll
            for (int mt = 0; mt < 2; mt++) {
                int r0 = (wm * 32 + mt * 16 + (lane >> 2)) * SAW;
                int r8 = r0 + 8 * SAW;
                ah[mt][0] = Ah[r0 + kb];     ah[mt][1] = Ah[r8 + kb];
                ah[mt][2] = Ah[r0 + kb + 4]; ah[mt][3] = Ah[r8 + kb + 4];
                al[mt][0] = Al[r0 + kb];     al[mt][1] = Al[r8 + kb];
                al[mt][2] = Al[r0 + kb + 4]; al[mt][3] = Al[r8 + kb + 4];
            }
#pragma unroll
            for (int nt = 0; nt < 8; nt++) {
                int nb = (wn * 64 + nt * 8 + (lane >> 2)) * SAW;
                unsigned bh[2] = { Bh[nb + kb], Bh[nb + kb + 4] };
                unsigned bl[2] = { Bl[nb + kb], Bl[nb + kb + 4] };
#pragma unroll
                for (int mt = 0; mt < 2; mt++) {
                    mma_bf16(acc[mt][nt], ah[mt], bh);   // hi*hi
                    mma_bf16(acc[mt][nt], ah[mt], bl);   // hi*lo
                    mma_bf16(acc[mt][nt], al[mt], bh);   // lo*hi
                }
            }
        }
        __syncthreads();
    }

    // Epilogue: +bias, store z (fp32 + fp16), fused zi/zj
    float s1[4] = {0.f, 0.f, 0.f, 0.f};
    float s2[4] = {0.f, 0.f, 0.f, 0.f};
#pragma unroll
    for (int mt = 0; mt < 2; mt++) {
#pragma unroll
        for (int nt = 0; nt < 8; nt++) {
            int c = wn * 64 + nt * 8 + 2 * (lane & 3);
            float b0 = bias[c], b1 = bias[c + 1];
            float v00 = acc[mt][nt][0] + b0;
            float v01 = acc[mt][nt][1] + b1;
            float v10 = acc[mt][nt][2] + b0;
            float v11 = acc[mt][nt][3] + b1;
            int r0 = rowBase + wm * 32 + mt * 16 + (lane >> 2);
            *(float2*)&g_z[(size_t)r0 * F_OUT + c]       = make_float2(v00, v01);
            *(float2*)&g_z[(size_t)(r0 + 8) * F_OUT + c] = make_float2(v10, v11);
            *(__half2*)&g_zh[(size_t)r0 * F_OUT + c]       = __floats2half2_rn(v00, v01);
            *(__half2*)&g_zh[(size_t)(r0 + 8) * F_OUT + c] = __floats2half2_rn(v10, v11);
            float a1c = a1v[c], a1c1 = a1v[c + 1];
            float a2c = a2v[c], a2c1 = a2v[c + 1];
            s1[mt * 2 + 0] += a1c * v00 + a1c1 * v01;
            s1[mt * 2 + 1] += a1c * v10 + a1c1 * v11;
            s2[mt * 2 + 0] += a2c * v00 + a2c1 * v01;
            s2[mt * 2 + 1] += a2c * v10 + a2c1 * v11;
        }
    }
#pragma unroll
    for (int i = 0; i < 4; i++) {
        s1[i] += __shfl_xor_sync(0xffffffffu, s1[i], 1);
        s1[i] += __shfl_xor_sync(0xffffffffu, s1[i], 2);
        s2[i] += __shfl_xor_sync(0xffffffffu, s2[i], 1);
        s2[i] += __shfl_xor_sync(0xffffffffu, s2[i], 2);
    }
    if ((lane & 3) == 0) {
#pragma unroll
        for (int i = 0; i < 4; i++) {
            int mt = i >> 1, h = i & 1;
            int rl = wm * 32 + mt * 16 + (lane >> 2) + h * 8;
            s_red1[rl][wn] = s1[i];
            s_red2[rl][wn] = s2[i];
        }
    }
    __syncthreads();
    if (tid < BM) {
        g_zi[rowBase + tid] = s_red1[tid][0] + s_red1[tid][1] + s_red1[tid][2] + s_red1[tid][3];
    } else if (tid < 2 * BM) {
        int r = tid - BM;
        g_zj[rowBase + r] = s_red2[r][0] + s_red2[r][1] + s_red2[r][2] + s_red2[r][3];
    }
}

// ---------------------------------------------------------------------------
// Fused flag kernel: ONE single-block launch (zero 8192 + scatter 4096),
// replacing two tiny kernels (each ~2-4us of in-graph launch overhead).
// ---------------------------------------------------------------------------
__global__ __launch_bounds__(1024) void flags_kernel(const int* __restrict__ mask)
{
    const int tid = threadIdx.x;
#pragma unroll
    for (int q = 0; q < NN / 1024; q++) g_flag[q * 1024 + tid] = 0;
    __syncthreads();
#pragma unroll
    for (int q = 0; q < MM / 1024; q++) g_flag[mask[q * 1024 + tid]] = 1;
}

// ---------------------------------------------------------------------------
// Kernel B: bitmask scan of adj rows of unique masked nodes -> neighbor
// lists. v4: 128-thread CTAs (64-bit mask per thread) so THREE scan CTAs
// co-reside with a GEMM CTA (128*46 = 5888 regs each vs 18432 free),
// tripling scan progress during the GEMM overlap window.
// ---------------------------------------------------------------------------
__global__ __launch_bounds__(128, 11) void scan_kernel(const float* __restrict__ adj)
{
    __shared__ int s_idx[MAXNBR];
    __shared__ int s_cnt;

    const int i = blockIdx.x;
    if (!g_flag[i]) return;
    const int tid = threadIdx.x;
    const int lane = tid & 31;

    if (tid == 0) s_cnt = 0;
    __syncthreads();

    const float4* arow = (const float4*)(adj + (size_t)i * NN);

    // 16 coalesced float4 loads per thread, folded into a 64-bit mask in two
    // batches of 8 (keeps <=8 float4 live -> low regs, MLP=8).
    unsigned long long msk = 0;
#pragma unroll
    for (int h = 0; h < 2; h++) {
        unsigned m32 = 0;
#pragma unroll
        for (int q = 0; q < 8; q++) {
            float4 v = arow[(h * 8 + q) * 128 + tid];
            m32 |= (unsigned)(v.x != 0.f) << (q * 4 + 0);
            m32 |= (unsigned)(v.y != 0.f) << (q * 4 + 1);
            m32 |= (unsigned)(v.z != 0.f) << (q * 4 + 2);
            m32 |= (unsigned)(v.w != 0.f) << (q * 4 + 3);
        }
        msk |= (unsigned long long)m32 << (h * 32);
    }

    // Single warp-inclusive prefix scan of per-thread counts (4 warps).
    int c = __popcll(msk);
    int pref = c;
#pragma unroll
    for (int d = 1; d < 32; d <<= 1) {
        int n = __shfl_up_sync(0xffffffffu, pref, d);
        if (lane >= d) pref += n;
    }
    int total = __shfl_sync(0xffffffffu, pref, 31);
    int base = 0;
    if (lane == 31) base = atomicAdd(&s_cnt, total);
    base = __shfl_sync(0xffffffffu, base, 31);
    int pos = base + pref - c;

    // Decode set bits: bit b -> float4 idx (b>>2)*128+tid, elem b&3
    //   -> column j = (b>>2)*512 + tid*4 + (b&3).
    while (msk) {
        int b = __ffsll(msk) - 1;
        msk &= msk - 1;
        int j = ((b >> 2) << 9) + tid * 4 + (b & 3);
        if (pos < MAXNBR) s_idx[pos++] = j;
    }
    __syncthreads();

    int cnt = s_cnt;
    if (cnt > MAXNBR) cnt = MAXNBR;
    for (int k = tid; k < cnt; k += 128)
        g_nbr[i * MAXNBR + k] = s_idx[k];
    if (tid == 0) g_cnt[i] = cnt;
}

// ---------------------------------------------------------------------------
// Kernel C [R9/R14]: per unique node, gather fp16 z over neighbors,
// closed-form attention combine vs fp32 z/zi/zj, relu, store g_h[node].
// ---------------------------------------------------------------------------
__global__ __launch_bounds__(128) void combine_kernel()
{
    __shared__ int s_idx[MAXNBR];

    const int i = blockIdx.x;
    if (!g_flag[i]) return;
    const int tid = threadIdx.x;
    const int cnt = g_cnt[i];

    for (int k = tid; k < cnt; k += 128) s_idx[k] = g_nbr[i * MAXNBR + k];
    __syncthreads();

    const __half2* zh2 = (const __half2*)g_zh;
    float ax = 0.f, ay = 0.f;
    int k = 0;
    for (; k + 8 <= cnt; k += 8) {
        float2 t[8];
#pragma unroll
        for (int u = 0; u < 8; u++) {
            __half2 h = zh2[(size_t)s_idx[k + u] * (F_OUT / 2) + tid];
            t[u] = __half22float2(h);
        }
#pragma unroll
        for (int u = 0; u < 8; u++) { ax += t[u].x; ay += t[u].y; }
    }
    for (; k < cnt; k++) {
        float2 t = __half22float2(zh2[(size_t)s_idx[k] * (F_OUT / 2) + tid]);
        ax += t.x; ay += t.y;
    }

    float2 zv = *(const float2*)&g_z[(size_t)i * F_OUT + 2 * tid];
    float vi = g_zi[i];
    float vj = g_zj[i];

    float x_off  = vi;
    float x_diag = vi + vj;
    float l_off  = x_off  > 0.f ? x_off  : NEG_SLOPE * x_off;
    float l_diag = x_diag > 0.f ? x_diag : NEG_SLOPE * x_diag;
    float e_off  = expf(l_off);
    float e_diag = expf(l_diag);
    float S = (float)(cnt - 1) * e_off + e_diag;
    float invS = 1.0f / S;
    float eS = e_off * invS, dS = e_diag * invS;

    float hx = zv.x - (eS * (ax - zv.x) + dS * zv.x);
    float hy = zv.y - (eS * (ay - zv.y) + dS * zv.y);
    *(float2*)&g_h[(size_t)i * F_OUT + 2 * tid] =
        make_float2(fmaxf(hx, 0.f), fmaxf(hy, 0.f));
}

// ---------------------------------------------------------------------------
// Kernel D: out[m] = g_h[mask[m]]   (flat float4 copy)
// ---------------------------------------------------------------------------
__global__ __launch_bounds__(256) void out_copy_kernel(
    const int* __restrict__ mask, float* __restrict__ out)
{
    int idx = blockIdx.x * 256 + threadIdx.x;    // over MM*64 float4 slots
    int m = idx >> 6;
    int t = idx & 63;
    if (m >= MM) return;
    int node = mask[m];
    const float4* src = (const float4*)(g_h + (size_t)node * F_OUT);
    ((float4*)(out + (size_t)m * F_OUT))[t] = src[t];
}

// ---------------------------------------------------------------------------
// Side stream + events (static init; serial fallback if creation fails)
// ---------------------------------------------------------------------------
namespace {
struct StreamRes {
    cudaStream_t s1 = nullptr;
    cudaEvent_t fork = nullptr, scan_done = nullptr;
    bool ok = false;
    StreamRes() {
        if (cudaStreamCreateWithFlags(&s1, cudaStreamNonBlocking) != cudaSuccess) return;
        if (cudaEventCreateWithFlags(&fork, cudaEventDisableTiming) != cudaSuccess) return;
        if (cudaEventCreateWithFlags(&scan_done, cudaEventDisableTiming) != cudaSuccess) return;
        ok = true;
    }
};
StreamRes g_sr;
}

// ---------------------------------------------------------------------------
// Launch.  Inputs: 0 adj, 1 eye (UNUSED), 2 feats, 3 node_mask, 4 W, 5 b,
//                  6 a_1, 7 a_2.   Output [M,256] f32.
// GEMM (256 thr, 184 regs) + up to 3 scan CTAs (128 thr, <=46 regs) per SM.
// ---------------------------------------------------------------------------
extern "C" void kernel_launch(void* const* d_in, const int* in_sizes, int n_in,
                              void* d_out, int out_size)
{
    const float* adj   = (const float*)d_in[0];
    const float* feats = (const float*)d_in[2];
    const int*   maskp = (const int*)  d_in[3];
    const float* Wm    = (const float*)d_in[4];
    const float* bias  = (const float*)d_in[5];
    const float* a1    = (const float*)d_in[6];
    const float* a2    = (const float*)d_in[7];
    float* out = (float*)d_out;

    cudaFuncSetAttribute(gemm_z_tc, cudaFuncAttributeMaxDynamicSharedMemorySize, GEMM_SMEM);

    if (g_sr.ok) {
        // Fork: GEMM on main stream; flags + scan chain on side stream.
        cudaEventRecord(g_sr.fork, 0);
        cudaStreamWaitEvent(g_sr.s1, g_sr.fork, 0);
        gemm_z_tc<<<NN / BM, 256, GEMM_SMEM>>>(feats, Wm, bias, a1, a2);
        flags_kernel<<<1, 1024, 0, g_sr.s1>>>(maskp);
        scan_kernel<<<NN, 128, 0, g_sr.s1>>>(adj);
        cudaEventRecord(g_sr.scan_done, g_sr.s1);
        cudaStreamWaitEvent(0, g_sr.scan_done, 0);
    } else {
        flags_kernel<<<1, 1024>>>(maskp);
        scan_kernel<<<NN, 128>>>(adj);
        gemm_z_tc<<<NN / BM, 256, GEMM_SMEM>>>(feats, Wm, bias, a1, a2);
    }

    combine_kernel<<<NN, 128>>>();
    out_copy_kernel<<<(MM * 64 + 255) / 256, 256>>>(maskp, out);
}